// round 4
// baseline (speedup 1.0000x reference)
#include <cuda_runtime.h>
#include <cuda_bf16.h>
#include <math.h>

// Problem constants
#define Ls 6
#define Hh 12
#define Dd 64
#define Cc_ 768
#define Vv 32000
#define Bb 2
#define Tt 1024
#define Ff 3072           // 4*C
#define Mm (Bb*Tt)        // 2048

// ---------------- scratch (device globals: alloc-free) ----------------
__device__ float d_h  [Mm*Cc_];
__device__ float d_ln [Mm*Cc_];
__device__ float d_q  [Mm*Cc_];
__device__ float d_k  [Mm*Cc_];
__device__ float d_v  [Mm*Cc_];
__device__ float d_att[Mm*Cc_];
__device__ float d_mid[Mm*Ff];

// ---------------- helpers ----------------
__device__ __forceinline__ float blockReduceSum256(float v) {
    __shared__ float sh[33];
    int lane = threadIdx.x & 31, wid = threadIdx.x >> 5;
#pragma unroll
    for (int o = 16; o; o >>= 1) v += __shfl_xor_sync(0xffffffffu, v, o);
    if (lane == 0) sh[wid] = v;
    __syncthreads();
    if (wid == 0) {
        float t = (lane < 8) ? sh[lane] : 0.f;
#pragma unroll
        for (int o = 4; o; o >>= 1) t += __shfl_xor_sync(0xffffffffu, t, o);
        if (lane == 0) sh[32] = t;
    }
    __syncthreads();
    float r = sh[32];
    __syncthreads();   // allow safe reuse of sh on a second call
    return r;
}

// ---------------- embedding ----------------
__global__ void embed_kernel(const int* __restrict__ x,
                             const float* __restrict__ tok,
                             const float* __restrict__ pos,
                             float* __restrict__ h) {
    int i = blockIdx.x * blockDim.x + threadIdx.x;
    if (i >= Mm * Cc_) return;
    int m = i / Cc_, c = i - m * Cc_;
    int t = m % Tt;
    h[i] = tok[(size_t)x[m] * Cc_ + c] + pos[(size_t)t * Cc_ + c];
}

// ---------------- layernorm (1 row / block, 256 threads) ----------------
__global__ __launch_bounds__(256) void ln_kernel(const float* __restrict__ x,
                                                 const float* __restrict__ g,
                                                 const float* __restrict__ b,
                                                 float* __restrict__ out) {
    int row = blockIdx.x;
    const float* xr = x + (size_t)row * Cc_;
    int tid = threadIdx.x;
    float v0 = xr[tid], v1 = xr[tid + 256], v2 = xr[tid + 512];
    float s = blockReduceSum256(v0 + v1 + v2);
    float mean = s * (1.f / Cc_);
    float e0 = v0 - mean, e1 = v1 - mean, e2 = v2 - mean;
    float s2 = blockReduceSum256(e0 * e0 + e1 * e1 + e2 * e2);
    float rstd = rsqrtf(s2 * (1.f / Cc_) + 1e-5f);
    float* orow = out + (size_t)row * Cc_;
    orow[tid]       = e0 * rstd * g[tid]       + b[tid];
    orow[tid + 256] = e1 * rstd * g[tid + 256] + b[tid + 256];
    orow[tid + 512] = e2 * rstd * g[tid + 512] + b[tid + 512];
}

// ---------------- main SGEMM: C = A(MxK) @ B(KxN) + bias [+resid][relu] ----------------
// 128x128 tile, BK=8, 256 threads, 8x8 per thread
template <bool RELU, bool RESID>
__global__ __launch_bounds__(256) void gemm128(const float* __restrict__ A,
                                               const float* __restrict__ Bw,
                                               const float* __restrict__ bias,
                                               const float* __restrict__ Rz,
                                               float* __restrict__ Co,
                                               int M, int N, int K) {
    __shared__ float As[8][128];
    __shared__ float Bs[8][128];
    int tid = threadIdx.x;
    int m0 = blockIdx.y * 128;
    int n0 = blockIdx.x * 128;
    int arow = tid >> 1, acol = (tid & 1) << 2;
    int brow = tid >> 5, bcol = (tid & 31) << 2;
    int trow = (tid >> 4) << 3;
    int tcol = (tid & 15) << 3;
    float acc[8][8] = {};
    const float* Ap = A + (size_t)(m0 + arow) * K + acol;
    const float* Bp = Bw + (size_t)brow * N + n0 + bcol;

    for (int k0 = 0; k0 < K; k0 += 8) {
        float4 a = *(const float4*)(Ap + k0);
        As[acol + 0][arow] = a.x;
        As[acol + 1][arow] = a.y;
        As[acol + 2][arow] = a.z;
        As[acol + 3][arow] = a.w;
        float4 bv = *(const float4*)(Bp + (size_t)k0 * N);
        *(float4*)&Bs[brow][bcol] = bv;
        __syncthreads();
#pragma unroll
        for (int kk = 0; kk < 8; ++kk) {
            float4 ra0 = *(const float4*)&As[kk][trow];
            float4 ra1 = *(const float4*)&As[kk][trow + 4];
            float4 rb0 = *(const float4*)&Bs[kk][tcol];
            float4 rb1 = *(const float4*)&Bs[kk][tcol + 4];
            float ra[8] = {ra0.x, ra0.y, ra0.z, ra0.w, ra1.x, ra1.y, ra1.z, ra1.w};
            float rb[8] = {rb0.x, rb0.y, rb0.z, rb0.w, rb1.x, rb1.y, rb1.z, rb1.w};
#pragma unroll
            for (int i = 0; i < 8; ++i)
#pragma unroll
                for (int j = 0; j < 8; ++j) acc[i][j] += ra[i] * rb[j];
        }
        __syncthreads();
    }
#pragma unroll
    for (int i = 0; i < 8; ++i) {
        int row = m0 + trow + i;
#pragma unroll
        for (int j = 0; j < 8; ++j) {
            int col = n0 + tcol + j;
            float v = acc[i][j] + bias[col];
            if (RELU) v = fmaxf(v, 0.f);
            if (RESID) v += Rz[(size_t)row * N + col];
            Co[(size_t)row * N + col] = v;
        }
    }
}

// ---------------- fused QKV GEMM: per head, N=64 ----------------
// grid (H, M/128), 256 threads, 8x4 per thread per output
__global__ __launch_bounds__(256) void qkv_kernel(const float* __restrict__ A,
                                                  const float* __restrict__ Wq,
                                                  const float* __restrict__ Wk,
                                                  const float* __restrict__ Wv,
                                                  float* __restrict__ Qo,
                                                  float* __restrict__ Ko,
                                                  float* __restrict__ Vo) {
    __shared__ float As[8][128];
    __shared__ float Bq[8][64];
    __shared__ float Bk[8][64];
    __shared__ float Bv[8][64];
    int tid = threadIdx.x;
    int hh = blockIdx.x;
    int m0 = blockIdx.y * 128;
    int arow = tid >> 1, acol = (tid & 1) << 2;
    int brow = tid >> 5, bcol = (tid & 31) << 1;   // float2 across 64 cols
    int trow = (tid >> 4) << 3;
    int tcol = (tid & 15) << 2;
    float aq[8][4] = {}, ak[8][4] = {}, av[8][4] = {};
    const float* Ap  = A  + (size_t)(m0 + arow) * Cc_ + acol;
    const float* Wqp = Wq + ((size_t)hh * Cc_ + brow) * Dd + bcol;
    const float* Wkp = Wk + ((size_t)hh * Cc_ + brow) * Dd + bcol;
    const float* Wvp = Wv + ((size_t)hh * Cc_ + brow) * Dd + bcol;

    for (int k0 = 0; k0 < Cc_; k0 += 8) {
        float4 a = *(const float4*)(Ap + k0);
        As[acol + 0][arow] = a.x;
        As[acol + 1][arow] = a.y;
        As[acol + 2][arow] = a.z;
        As[acol + 3][arow] = a.w;
        size_t woff = (size_t)k0 * Dd;
        *(float2*)&Bq[brow][bcol] = *(const float2*)(Wqp + woff);
        *(float2*)&Bk[brow][bcol] = *(const float2*)(Wkp + woff);
        *(float2*)&Bv[brow][bcol] = *(const float2*)(Wvp + woff);
        __syncthreads();
#pragma unroll
        for (int kk = 0; kk < 8; ++kk) {
            float4 ra0 = *(const float4*)&As[kk][trow];
            float4 ra1 = *(const float4*)&As[kk][trow + 4];
            float ra[8] = {ra0.x, ra0.y, ra0.z, ra0.w, ra1.x, ra1.y, ra1.z, ra1.w};
            float4 rq = *(const float4*)&Bq[kk][tcol];
            float4 rk = *(const float4*)&Bk[kk][tcol];
            float4 rv = *(const float4*)&Bv[kk][tcol];
            float q4[4] = {rq.x, rq.y, rq.z, rq.w};
            float k4[4] = {rk.x, rk.y, rk.z, rk.w};
            float v4[4] = {rv.x, rv.y, rv.z, rv.w};
#pragma unroll
            for (int i = 0; i < 8; ++i)
#pragma unroll
                for (int j = 0; j < 4; ++j) {
                    aq[i][j] += ra[i] * q4[j];
                    ak[i][j] += ra[i] * k4[j];
                    av[i][j] += ra[i] * v4[j];
                }
        }
        __syncthreads();
    }
#pragma unroll
    for (int i = 0; i < 8; ++i) {
        int row = m0 + trow + i;
        int bb = row / Tt, t = row % Tt;
        size_t base = (((size_t)bb * Hh + hh) * Tt + t) * Dd + tcol;
        *(float4*)&Qo[base] = make_float4(aq[i][0], aq[i][1], aq[i][2], aq[i][3]);
        *(float4*)&Ko[base] = make_float4(ak[i][0], ak[i][1], ak[i][2], ak[i][3]);
        *(float4*)&Vo[base] = make_float4(av[i][0], av[i][1], av[i][2], av[i][3]);
    }
}

// ---------------- flash attention (fp32, online softmax) ----------------
// grid (T/128, B*H), 128 threads; each thread owns one query row
__global__ __launch_bounds__(128) void flash_kernel(const float* __restrict__ Q,
                                                    const float* __restrict__ K,
                                                    const float* __restrict__ V,
                                                    float* __restrict__ O) {
    __shared__ float ks[64][64];
    __shared__ float vs[64][64];
    int qb = blockIdx.x;
    int bh = blockIdx.y;
    int bb = bh / Hh, hh = bh % Hh;
    int tid = threadIdx.x;
    int qi = qb * 128 + tid;

    const float scale = rsqrtf((float)Cc_);
    float qreg[64];
    const float* Qp = Q + ((size_t)bh * Tt + qi) * Dd;
#pragma unroll
    for (int d = 0; d < 64; ++d) qreg[d] = Qp[d] * scale;

    float m = -1e30f, lsum = 0.f;
    float o[64];
#pragma unroll
    for (int d = 0; d < 64; ++d) o[d] = 0.f;

    int numkt = 2 * (qb + 1);
    for (int kt = 0; kt < numkt; ++kt) {
        __syncthreads();
        const float* Kp = K + ((size_t)bh * Tt + kt * 64) * Dd;
        const float* Vp = V + ((size_t)bh * Tt + kt * 64) * Dd;
#pragma unroll
        for (int i = 0; i < 32; ++i) {
            int e = i * 128 + tid;
            ((float*)ks)[e] = Kp[e];
            ((float*)vs)[e] = Vp[e];
        }
        __syncthreads();
        int jend = qi - kt * 64 + 1;          // causal: key index <= qi
        if (jend > 64) jend = 64;
        for (int j = 0; j < jend; ++j) {
            float s = 0.f;
#pragma unroll
            for (int d = 0; d < 64; ++d) s += qreg[d] * ks[j][d];
            float mnew = fmaxf(m, s);
            float corr = __expf(m - mnew);
            float p = __expf(s - mnew);
            lsum = lsum * corr + p;
#pragma unroll
            for (int d = 0; d < 64; ++d) o[d] = o[d] * corr + p * vs[j][d];
            m = mnew;
        }
    }
    float inv = 1.f / lsum;
    float* Op = O + ((size_t)bb * Tt + qi) * Cc_ + hh * Dd;   // (B,T,H*D)
#pragma unroll
    for (int d = 0; d < 64; ++d) Op[d] = o[d] * inv;
}

// ---------------- launch ----------------
extern "C" void kernel_launch(void* const* d_in, const int* in_sizes, int n_in,
                              void* d_out, int out_size) {
    const int*   x     = (const int*)d_in[0];
    const float* tok   = (const float*)d_in[1];
    const float* pos   = (const float*)d_in[2];
    const float* Wq    = (const float*)d_in[3];
    const float* Wk    = (const float*)d_in[4];
    const float* Wv    = (const float*)d_in[5];
    const float* Wo    = (const float*)d_in[6];
    const float* bo    = (const float*)d_in[7];
    const float* ln1g  = (const float*)d_in[8];
    const float* ln1b  = (const float*)d_in[9];
    const float* ln2g  = (const float*)d_in[10];
    const float* ln2b  = (const float*)d_in[11];
    const float* W1    = (const float*)d_in[12];
    const float* b1    = (const float*)d_in[13];
    const float* W2    = (const float*)d_in[14];
    const float* b2    = (const float*)d_in[15];
    const float* lnfg  = (const float*)d_in[16];
    const float* lnfb  = (const float*)d_in[17];
    const float* Wh    = (const float*)d_in[18];
    const float* bh    = (const float*)d_in[19];
    float* out = (float*)d_out;

    float *h, *ln, *q, *k, *v, *att, *mid;
    cudaGetSymbolAddress((void**)&h,   d_h);
    cudaGetSymbolAddress((void**)&ln,  d_ln);
    cudaGetSymbolAddress((void**)&q,   d_q);
    cudaGetSymbolAddress((void**)&k,   d_k);
    cudaGetSymbolAddress((void**)&v,   d_v);
    cudaGetSymbolAddress((void**)&att, d_att);
    cudaGetSymbolAddress((void**)&mid, d_mid);

    embed_kernel<<<(Mm * Cc_ + 255) / 256, 256>>>(x, tok, pos, h);

    for (int l = 0; l < Ls; ++l) {
        ln_kernel<<<Mm, 256>>>(h, ln1g + l * Cc_, ln1b + l * Cc_, ln);
        qkv_kernel<<<dim3(Hh, Mm / 128), 256>>>(
            ln, Wq + (size_t)l * Hh * Cc_ * Dd, Wk + (size_t)l * Hh * Cc_ * Dd,
            Wv + (size_t)l * Hh * Cc_ * Dd, q, k, v);
        flash_kernel<<<dim3(Tt / 128, Bb * Hh), 128>>>(q, k, v, att);
        gemm128<false, true><<<dim3(Cc_ / 128, Mm / 128), 256>>>(
            att, Wo + (size_t)l * Cc_ * Cc_, bo + l * Cc_, h, h, Mm, Cc_, Cc_);
        ln_kernel<<<Mm, 256>>>(h, ln2g + l * Cc_, ln2b + l * Cc_, ln);
        gemm128<true, false><<<dim3(Ff / 128, Mm / 128), 256>>>(
            ln, W1 + (size_t)l * Cc_ * Ff, b1 + l * Ff, nullptr, mid, Mm, Ff, Cc_);
        gemm128<false, true><<<dim3(Cc_ / 128, Mm / 128), 256>>>(
            mid, W2 + (size_t)l * Ff * Cc_, b2 + l * Cc_, h, h, Mm, Cc_, Ff);
    }

    ln_kernel<<<Mm, 256>>>(h, lnfg, lnfb, ln);
    gemm128<false, false><<<dim3(Vv / 128, Mm / 128), 256>>>(
        ln, Wh, bh, nullptr, out, Mm, Vv, Cc_);
}

// round 8
// speedup vs baseline: 1.0003x; 1.0003x over previous
#include <cuda_runtime.h>
#include <cuda_bf16.h>
#include <math.h>

// Problem constants
#define Ls 6
#define Hh 12
#define Dd 64
#define Cc_ 768
#define Vv 32000
#define Bb 2
#define Tt 1024
#define Ff 3072           // 4*C
#define Mm (Bb*Tt)        // 2048

// ---------------- scratch (device globals: alloc-free) ----------------
__device__ float d_h  [Mm*Cc_];
__device__ float d_ln [Mm*Cc_];
__device__ float d_q  [Mm*Cc_];
__device__ float d_k  [Mm*Cc_];
__device__ float d_v  [Mm*Cc_];
__device__ float d_att[Mm*Cc_];
__device__ float d_mid[Mm*Ff];

// ---------------- helpers ----------------
__device__ __forceinline__ float blockReduceSum256(float v) {
    __shared__ float sh[33];
    int lane = threadIdx.x & 31, wid = threadIdx.x >> 5;
#pragma unroll
    for (int o = 16; o; o >>= 1) v += __shfl_xor_sync(0xffffffffu, v, o);
    if (lane == 0) sh[wid] = v;
    __syncthreads();
    if (wid == 0) {
        float t = (lane < 8) ? sh[lane] : 0.f;
#pragma unroll
        for (int o = 4; o; o >>= 1) t += __shfl_xor_sync(0xffffffffu, t, o);
        if (lane == 0) sh[32] = t;
    }
    __syncthreads();
    float r = sh[32];
    __syncthreads();   // allow safe reuse of sh on a second call
    return r;
}

// ---------------- embedding ----------------
__global__ void embed_kernel(const int* __restrict__ x,
                             const float* __restrict__ tok,
                             const float* __restrict__ pos,
                             float* __restrict__ h) {
    int i = blockIdx.x * blockDim.x + threadIdx.x;
    if (i >= Mm * Cc_) return;
    int m = i / Cc_, c = i - m * Cc_;
    int t = m % Tt;
    h[i] = tok[(size_t)x[m] * Cc_ + c] + pos[(size_t)t * Cc_ + c];
}

// ---------------- layernorm (1 row / block, 256 threads) ----------------
__global__ __launch_bounds__(256) void ln_kernel(const float* __restrict__ x,
                                                 const float* __restrict__ g,
                                                 const float* __restrict__ b,
                                                 float* __restrict__ out) {
    int row = blockIdx.x;
    const float* xr = x + (size_t)row * Cc_;
    int tid = threadIdx.x;
    float v0 = xr[tid], v1 = xr[tid + 256], v2 = xr[tid + 512];
    float s = blockReduceSum256(v0 + v1 + v2);
    float mean = s * (1.f / Cc_);
    float e0 = v0 - mean, e1 = v1 - mean, e2 = v2 - mean;
    float s2 = blockReduceSum256(e0 * e0 + e1 * e1 + e2 * e2);
    float rstd = rsqrtf(s2 * (1.f / Cc_) + 1e-5f);
    float* orow = out + (size_t)row * Cc_;
    orow[tid]       = e0 * rstd * g[tid]       + b[tid];
    orow[tid + 256] = e1 * rstd * g[tid + 256] + b[tid + 256];
    orow[tid + 512] = e2 * rstd * g[tid + 512] + b[tid + 512];
}

// ---------------- main SGEMM: C = A(MxK) @ B(KxN) + bias [+resid][relu] ----------------
// 128x128 tile, BK=8, 256 threads, 8x8 per thread
template <bool RELU, bool RESID>
__global__ __launch_bounds__(256) void gemm128(const float* __restrict__ A,
                                               const float* __restrict__ Bw,
                                               const float* __restrict__ bias,
                                               const float* __restrict__ Rz,
                                               float* __restrict__ Co,
                                               int M, int N, int K) {
    __shared__ float As[8][128];
    __shared__ float Bs[8][128];
    int tid = threadIdx.x;
    int m0 = blockIdx.y * 128;
    int n0 = blockIdx.x * 128;
    int arow = tid >> 1, acol = (tid & 1) << 2;
    int brow = tid >> 5, bcol = (tid & 31) << 2;
    int trow = (tid >> 4) << 3;
    int tcol = (tid & 15) << 3;
    float acc[8][8] = {};
    const float* Ap = A + (size_t)(m0 + arow) * K + acol;
    const float* Bp = Bw + (size_t)brow * N + n0 + bcol;

    for (int k0 = 0; k0 < K; k0 += 8) {
        float4 a = *(const float4*)(Ap + k0);
        As[acol + 0][arow] = a.x;
        As[acol + 1][arow] = a.y;
        As[acol + 2][arow] = a.z;
        As[acol + 3][arow] = a.w;
        float4 bv = *(const float4*)(Bp + (size_t)k0 * N);
        *(float4*)&Bs[brow][bcol] = bv;
        __syncthreads();
#pragma unroll
        for (int kk = 0; kk < 8; ++kk) {
            float4 ra0 = *(const float4*)&As[kk][trow];
            float4 ra1 = *(const float4*)&As[kk][trow + 4];
            float4 rb0 = *(const float4*)&Bs[kk][tcol];
            float4 rb1 = *(const float4*)&Bs[kk][tcol + 4];
            float ra[8] = {ra0.x, ra0.y, ra0.z, ra0.w, ra1.x, ra1.y, ra1.z, ra1.w};
            float rb[8] = {rb0.x, rb0.y, rb0.z, rb0.w, rb1.x, rb1.y, rb1.z, rb1.w};
#pragma unroll
            for (int i = 0; i < 8; ++i)
#pragma unroll
                for (int j = 0; j < 8; ++j) acc[i][j] += ra[i] * rb[j];
        }
        __syncthreads();
    }
#pragma unroll
    for (int i = 0; i < 8; ++i) {
        int row = m0 + trow + i;
#pragma unroll
        for (int j = 0; j < 8; ++j) {
            int col = n0 + tcol + j;
            float v = acc[i][j] + bias[col];
            if (RELU) v = fmaxf(v, 0.f);
            if (RESID) v += Rz[(size_t)row * N + col];
            Co[(size_t)row * N + col] = v;
        }
    }
}

// ---------------- fused QKV GEMM: per head, N=64 ----------------
// grid (H, M/128), 256 threads, 8x4 per thread per output
__global__ __launch_bounds__(256) void qkv_kernel(const float* __restrict__ A,
                                                  const float* __restrict__ Wq,
                                                  const float* __restrict__ Wk,
                                                  const float* __restrict__ Wv,
                                                  float* __restrict__ Qo,
                                                  float* __restrict__ Ko,
                                                  float* __restrict__ Vo) {
    __shared__ float As[8][128];
    __shared__ float Bq[8][64];
    __shared__ float Bk[8][64];
    __shared__ float Bv[8][64];
    int tid = threadIdx.x;
    int hh = blockIdx.x;
    int m0 = blockIdx.y * 128;
    int arow = tid >> 1, acol = (tid & 1) << 2;
    int brow = tid >> 5, bcol = (tid & 31) << 1;   // float2 across 64 cols
    int trow = (tid >> 4) << 3;
    int tcol = (tid & 15) << 2;
    float aq[8][4] = {}, ak[8][4] = {}, av[8][4] = {};
    const float* Ap  = A  + (size_t)(m0 + arow) * Cc_ + acol;
    const float* Wqp = Wq + ((size_t)hh * Cc_ + brow) * Dd + bcol;
    const float* Wkp = Wk + ((size_t)hh * Cc_ + brow) * Dd + bcol;
    const float* Wvp = Wv + ((size_t)hh * Cc_ + brow) * Dd + bcol;

    for (int k0 = 0; k0 < Cc_; k0 += 8) {
        float4 a = *(const float4*)(Ap + k0);
        As[acol + 0][arow] = a.x;
        As[acol + 1][arow] = a.y;
        As[acol + 2][arow] = a.z;
        As[acol + 3][arow] = a.w;
        size_t woff = (size_t)k0 * Dd;
        *(float2*)&Bq[brow][bcol] = *(const float2*)(Wqp + woff);
        *(float2*)&Bk[brow][bcol] = *(const float2*)(Wkp + woff);
        *(float2*)&Bv[brow][bcol] = *(const float2*)(Wvp + woff);
        __syncthreads();
#pragma unroll
        for (int kk = 0; kk < 8; ++kk) {
            float4 ra0 = *(const float4*)&As[kk][trow];
            float4 ra1 = *(const float4*)&As[kk][trow + 4];
            float ra[8] = {ra0.x, ra0.y, ra0.z, ra0.w, ra1.x, ra1.y, ra1.z, ra1.w};
            float4 rq = *(const float4*)&Bq[kk][tcol];
            float4 rk = *(const float4*)&Bk[kk][tcol];
            float4 rv = *(const float4*)&Bv[kk][tcol];
            float q4[4] = {rq.x, rq.y, rq.z, rq.w};
            float k4[4] = {rk.x, rk.y, rk.z, rk.w};
            float v4[4] = {rv.x, rv.y, rv.z, rv.w};
#pragma unroll
            for (int i = 0; i < 8; ++i)
#pragma unroll
                for (int j = 0; j < 4; ++j) {
                    aq[i][j] += ra[i] * q4[j];
                    ak[i][j] += ra[i] * k4[j];
                    av[i][j] += ra[i] * v4[j];
                }
        }
        __syncthreads();
    }
#pragma unroll
    for (int i = 0; i < 8; ++i) {
        int row = m0 + trow + i;
        int bb = row / Tt, t = row % Tt;
        size_t base = (((size_t)bb * Hh + hh) * Tt + t) * Dd + tcol;
        *(float4*)&Qo[base] = make_float4(aq[i][0], aq[i][1], aq[i][2], aq[i][3]);
        *(float4*)&Ko[base] = make_float4(ak[i][0], ak[i][1], ak[i][2], ak[i][3]);
        *(float4*)&Vo[base] = make_float4(av[i][0], av[i][1], av[i][2], av[i][3]);
    }
}

// ---------------- flash attention (fp32, online softmax) ----------------
// grid (T/128, B*H), 128 threads; each thread owns one query row
__global__ __launch_bounds__(128) void flash_kernel(const float* __restrict__ Q,
                                                    const float* __restrict__ K,
                                                    const float* __restrict__ V,
                                                    float* __restrict__ O) {
    __shared__ float ks[64][64];
    __shared__ float vs[64][64];
    int qb = blockIdx.x;
    int bh = blockIdx.y;
    int bb = bh / Hh, hh = bh % Hh;
    int tid = threadIdx.x;
    int qi = qb * 128 + tid;

    const float scale = rsqrtf((float)Cc_);
    float qreg[64];
    const float* Qp = Q + ((size_t)bh * Tt + qi) * Dd;
#pragma unroll
    for (int d = 0; d < 64; ++d) qreg[d] = Qp[d] * scale;

    float m = -1e30f, lsum = 0.f;
    float o[64];
#pragma unroll
    for (int d = 0; d < 64; ++d) o[d] = 0.f;

    int numkt = 2 * (qb + 1);
    for (int kt = 0; kt < numkt; ++kt) {
        __syncthreads();
        const float* Kp = K + ((size_t)bh * Tt + kt * 64) * Dd;
        const float* Vp = V + ((size_t)bh * Tt + kt * 64) * Dd;
#pragma unroll
        for (int i = 0; i < 32; ++i) {
            int e = i * 128 + tid;
            ((float*)ks)[e] = Kp[e];
            ((float*)vs)[e] = Vp[e];
        }
        __syncthreads();
        int jend = qi - kt * 64 + 1;          // causal: key index <= qi
        if (jend > 64) jend = 64;
        for (int j = 0; j < jend; ++j) {
            float s = 0.f;
#pragma unroll
            for (int d = 0; d < 64; ++d) s += qreg[d] * ks[j][d];
            float mnew = fmaxf(m, s);
            float corr = __expf(m - mnew);
            float p = __expf(s - mnew);
            lsum = lsum * corr + p;
#pragma unroll
            for (int d = 0; d < 64; ++d) o[d] = o[d] * corr + p * vs[j][d];
            m = mnew;
        }
    }
    float inv = 1.f / lsum;
    float* Op = O + ((size_t)bb * Tt + qi) * Cc_ + hh * Dd;   // (B,T,H*D)
#pragma unroll
    for (int d = 0; d < 64; ++d) Op[d] = o[d] * inv;
}

// ---------------- launch ----------------
extern "C" void kernel_launch(void* const* d_in, const int* in_sizes, int n_in,
                              void* d_out, int out_size) {
    const int*   x     = (const int*)d_in[0];
    const float* tok   = (const float*)d_in[1];
    const float* pos   = (const float*)d_in[2];
    const float* Wq    = (const float*)d_in[3];
    const float* Wk    = (const float*)d_in[4];
    const float* Wv    = (const float*)d_in[5];
    const float* Wo    = (const float*)d_in[6];
    const float* bo    = (const float*)d_in[7];
    const float* ln1g  = (const float*)d_in[8];
    const float* ln1b  = (const float*)d_in[9];
    const float* ln2g  = (const float*)d_in[10];
    const float* ln2b  = (const float*)d_in[11];
    const float* W1    = (const float*)d_in[12];
    const float* b1    = (const float*)d_in[13];
    const float* W2    = (const float*)d_in[14];
    const float* b2    = (const float*)d_in[15];
    const float* lnfg  = (const float*)d_in[16];
    const float* lnfb  = (const float*)d_in[17];
    const float* Wh    = (const float*)d_in[18];
    const float* bh    = (const float*)d_in[19];
    float* out = (float*)d_out;

    float *h, *ln, *q, *k, *v, *att, *mid;
    cudaGetSymbolAddress((void**)&h,   d_h);
    cudaGetSymbolAddress((void**)&ln,  d_ln);
    cudaGetSymbolAddress((void**)&q,   d_q);
    cudaGetSymbolAddress((void**)&k,   d_k);
    cudaGetSymbolAddress((void**)&v,   d_v);
    cudaGetSymbolAddress((void**)&att, d_att);
    cudaGetSymbolAddress((void**)&mid, d_mid);

    embed_kernel<<<(Mm * Cc_ + 255) / 256, 256>>>(x, tok, pos, h);

    for (int l = 0; l < Ls; ++l) {
        ln_kernel<<<Mm, 256>>>(h, ln1g + l * Cc_, ln1b + l * Cc_, ln);
        qkv_kernel<<<dim3(Hh, Mm / 128), 256>>>(
            ln, Wq + (size_t)l * Hh * Cc_ * Dd, Wk + (size_t)l * Hh * Cc_ * Dd,
            Wv + (size_t)l * Hh * Cc_ * Dd, q, k, v);
        flash_kernel<<<dim3(Tt / 128, Bb * Hh), 128>>>(q, k, v, att);
        gemm128<false, true><<<dim3(Cc_ / 128, Mm / 128), 256>>>(
            att, Wo + (size_t)l * Cc_ * Cc_, bo + l * Cc_, h, h, Mm, Cc_, Cc_);
        ln_kernel<<<Mm, 256>>>(h, ln2g + l * Cc_, ln2b + l * Cc_, ln);
        gemm128<true, false><<<dim3(Ff / 128, Mm / 128), 256>>>(
            ln, W1 + (size_t)l * Cc_ * Ff, b1 + l * Ff, nullptr, mid, Mm, Ff, Cc_);
        gemm128<false, true><<<dim3(Cc_ / 128, Mm / 128), 256>>>(
            mid, W2 + (size_t)l * Ff * Cc_, b2 + l * Cc_, h, h, Mm, Cc_, Ff);
    }

    ln_kernel<<<Mm, 256>>>(h, lnfg, lnfb, ln);
    gemm128<false, false><<<dim3(Vv / 128, Mm / 128), 256>>>(
        ln, Wh, bh, nullptr, out, Mm, Vv, Cc_);
}

// round 9
// speedup vs baseline: 1.0038x; 1.0034x over previous
#include <cuda_runtime.h>
#include <cuda_bf16.h>
#include <math.h>

// Problem constants
#define Ls 6
#define Hh 12
#define Dd 64
#define Cc_ 768
#define Vv 32000
#define Bb 2
#define Tt 1024
#define Ff 3072           // 4*C
#define Mm (Bb*Tt)        // 2048

// ---------------- scratch (device globals: alloc-free) ----------------
__device__ float d_h  [Mm*Cc_];
__device__ float d_ln [Mm*Cc_];
__device__ float d_q  [Mm*Cc_];
__device__ float d_k  [Mm*Cc_];
__device__ float d_v  [Mm*Cc_];
__device__ float d_att[Mm*Cc_];
__device__ float d_mid[Mm*Ff];

// ---------------- helpers ----------------
__device__ __forceinline__ float blockReduceSum256(float v) {
    __shared__ float sh[33];
    int lane = threadIdx.x & 31, wid = threadIdx.x >> 5;
#pragma unroll
    for (int o = 16; o; o >>= 1) v += __shfl_xor_sync(0xffffffffu, v, o);
    if (lane == 0) sh[wid] = v;
    __syncthreads();
    if (wid == 0) {
        float t = (lane < 8) ? sh[lane] : 0.f;
#pragma unroll
        for (int o = 4; o; o >>= 1) t += __shfl_xor_sync(0xffffffffu, t, o);
        if (lane == 0) sh[32] = t;
    }
    __syncthreads();
    float r = sh[32];
    __syncthreads();   // allow safe reuse of sh on a second call
    return r;
}

// ---------------- embedding ----------------
__global__ void embed_kernel(const int* __restrict__ x,
                             const float* __restrict__ tok,
                             const float* __restrict__ pos,
                             float* __restrict__ h) {
    int i = blockIdx.x * blockDim.x + threadIdx.x;
    if (i >= Mm * Cc_) return;
    int m = i / Cc_, c = i - m * Cc_;
    int t = m % Tt;
    h[i] = tok[(size_t)x[m] * Cc_ + c] + pos[(size_t)t * Cc_ + c];
}

// ---------------- layernorm (1 row / block, 256 threads) ----------------
__global__ __launch_bounds__(256) void ln_kernel(const float* __restrict__ x,
                                                 const float* __restrict__ g,
                                                 const float* __restrict__ b,
                                                 float* __restrict__ out) {
    int row = blockIdx.x;
    const float* xr = x + (size_t)row * Cc_;
    int tid = threadIdx.x;
    float v0 = xr[tid], v1 = xr[tid + 256], v2 = xr[tid + 512];
    float s = blockReduceSum256(v0 + v1 + v2);
    float mean = s * (1.f / Cc_);
    float e0 = v0 - mean, e1 = v1 - mean, e2 = v2 - mean;
    float s2 = blockReduceSum256(e0 * e0 + e1 * e1 + e2 * e2);
    float rstd = rsqrtf(s2 * (1.f / Cc_) + 1e-5f);
    float* orow = out + (size_t)row * Cc_;
    orow[tid]       = e0 * rstd * g[tid]       + b[tid];
    orow[tid + 256] = e1 * rstd * g[tid + 256] + b[tid + 256];
    orow[tid + 512] = e2 * rstd * g[tid + 512] + b[tid + 512];
}

// ---------------- main SGEMM: C = A(MxK) @ B(KxN) + bias [+resid][relu] ----------------
// 128x128 tile, BK=8, 256 threads, 8x8 per thread
template <bool RELU, bool RESID>
__global__ __launch_bounds__(256) void gemm128(const float* __restrict__ A,
                                               const float* __restrict__ Bw,
                                               const float* __restrict__ bias,
                                               const float* __restrict__ Rz,
                                               float* __restrict__ Co,
                                               int M, int N, int K) {
    __shared__ float As[8][128];
    __shared__ float Bs[8][128];
    int tid = threadIdx.x;
    int m0 = blockIdx.y * 128;
    int n0 = blockIdx.x * 128;
    int arow = tid >> 1, acol = (tid & 1) << 2;
    int brow = tid >> 5, bcol = (tid & 31) << 2;
    int trow = (tid >> 4) << 3;
    int tcol = (tid & 15) << 3;
    float acc[8][8] = {};
    const float* Ap = A + (size_t)(m0 + arow) * K + acol;
    const float* Bp = Bw + (size_t)brow * N + n0 + bcol;

    for (int k0 = 0; k0 < K; k0 += 8) {
        float4 a = *(const float4*)(Ap + k0);
        As[acol + 0][arow] = a.x;
        As[acol + 1][arow] = a.y;
        As[acol + 2][arow] = a.z;
        As[acol + 3][arow] = a.w;
        float4 bv = *(const float4*)(Bp + (size_t)k0 * N);
        *(float4*)&Bs[brow][bcol] = bv;
        __syncthreads();
#pragma unroll
        for (int kk = 0; kk < 8; ++kk) {
            float4 ra0 = *(const float4*)&As[kk][trow];
            float4 ra1 = *(const float4*)&As[kk][trow + 4];
            float4 rb0 = *(const float4*)&Bs[kk][tcol];
            float4 rb1 = *(const float4*)&Bs[kk][tcol + 4];
            float ra[8] = {ra0.x, ra0.y, ra0.z, ra0.w, ra1.x, ra1.y, ra1.z, ra1.w};
            float rb[8] = {rb0.x, rb0.y, rb0.z, rb0.w, rb1.x, rb1.y, rb1.z, rb1.w};
#pragma unroll
            for (int i = 0; i < 8; ++i)
#pragma unroll
                for (int j = 0; j < 8; ++j) acc[i][j] += ra[i] * rb[j];
        }
        __syncthreads();
    }
#pragma unroll
    for (int i = 0; i < 8; ++i) {
        int row = m0 + trow + i;
#pragma unroll
        for (int j = 0; j < 8; ++j) {
            int col = n0 + tcol + j;
            float v = acc[i][j] + bias[col];
            if (RELU) v = fmaxf(v, 0.f);
            if (RESID) v += Rz[(size_t)row * N + col];
            Co[(size_t)row * N + col] = v;
        }
    }
}

// ---------------- fused QKV GEMM: per head, N=64 ----------------
// grid (H, M/128), 256 threads, 8x4 per thread per output
__global__ __launch_bounds__(256) void qkv_kernel(const float* __restrict__ A,
                                                  const float* __restrict__ Wq,
                                                  const float* __restrict__ Wk,
                                                  const float* __restrict__ Wv,
                                                  float* __restrict__ Qo,
                                                  float* __restrict__ Ko,
                                                  float* __restrict__ Vo) {
    __shared__ float As[8][128];
    __shared__ float Bq[8][64];
    __shared__ float Bk[8][64];
    __shared__ float Bv[8][64];
    int tid = threadIdx.x;
    int hh = blockIdx.x;
    int m0 = blockIdx.y * 128;
    int arow = tid >> 1, acol = (tid & 1) << 2;
    int brow = tid >> 5, bcol = (tid & 31) << 1;   // float2 across 64 cols
    int trow = (tid >> 4) << 3;
    int tcol = (tid & 15) << 2;
    float aq[8][4] = {}, ak[8][4] = {}, av[8][4] = {};
    const float* Ap  = A  + (size_t)(m0 + arow) * Cc_ + acol;
    const float* Wqp = Wq + ((size_t)hh * Cc_ + brow) * Dd + bcol;
    const float* Wkp = Wk + ((size_t)hh * Cc_ + brow) * Dd + bcol;
    const float* Wvp = Wv + ((size_t)hh * Cc_ + brow) * Dd + bcol;

    for (int k0 = 0; k0 < Cc_; k0 += 8) {
        float4 a = *(const float4*)(Ap + k0);
        As[acol + 0][arow] = a.x;
        As[acol + 1][arow] = a.y;
        As[acol + 2][arow] = a.z;
        As[acol + 3][arow] = a.w;
        size_t woff = (size_t)k0 * Dd;
        *(float2*)&Bq[brow][bcol] = *(const float2*)(Wqp + woff);
        *(float2*)&Bk[brow][bcol] = *(const float2*)(Wkp + woff);
        *(float2*)&Bv[brow][bcol] = *(const float2*)(Wvp + woff);
        __syncthreads();
#pragma unroll
        for (int kk = 0; kk < 8; ++kk) {
            float4 ra0 = *(const float4*)&As[kk][trow];
            float4 ra1 = *(const float4*)&As[kk][trow + 4];
            float ra[8] = {ra0.x, ra0.y, ra0.z, ra0.w, ra1.x, ra1.y, ra1.z, ra1.w};
            float4 rq = *(const float4*)&Bq[kk][tcol];
            float4 rk = *(const float4*)&Bk[kk][tcol];
            float4 rv = *(const float4*)&Bv[kk][tcol];
            float q4[4] = {rq.x, rq.y, rq.z, rq.w};
            float k4[4] = {rk.x, rk.y, rk.z, rk.w};
            float v4[4] = {rv.x, rv.y, rv.z, rv.w};
#pragma unroll
            for (int i = 0; i < 8; ++i)
#pragma unroll
                for (int j = 0; j < 4; ++j) {
                    aq[i][j] += ra[i] * q4[j];
                    ak[i][j] += ra[i] * k4[j];
                    av[i][j] += ra[i] * v4[j];
                }
        }
        __syncthreads();
    }
#pragma unroll
    for (int i = 0; i < 8; ++i) {
        int row = m0 + trow + i;
        int bb = row / Tt, t = row % Tt;
        size_t base = (((size_t)bb * Hh + hh) * Tt + t) * Dd + tcol;
        *(float4*)&Qo[base] = make_float4(aq[i][0], aq[i][1], aq[i][2], aq[i][3]);
        *(float4*)&Ko[base] = make_float4(ak[i][0], ak[i][1], ak[i][2], ak[i][3]);
        *(float4*)&Vo[base] = make_float4(av[i][0], av[i][1], av[i][2], av[i][3]);
    }
}

// ---------------- flash attention (fp32, online softmax) ----------------
// grid (T/128, B*H), 128 threads; each thread owns one query row
__global__ __launch_bounds__(128) void flash_kernel(const float* __restrict__ Q,
                                                    const float* __restrict__ K,
                                                    const float* __restrict__ V,
                                                    float* __restrict__ O) {
    __shared__ float ks[64][64];
    __shared__ float vs[64][64];
    int qb = blockIdx.x;
    int bh = blockIdx.y;
    int bb = bh / Hh, hh = bh % Hh;
    int tid = threadIdx.x;
    int qi = qb * 128 + tid;

    const float scale = rsqrtf((float)Cc_);
    float qreg[64];
    const float* Qp = Q + ((size_t)bh * Tt + qi) * Dd;
#pragma unroll
    for (int d = 0; d < 64; ++d) qreg[d] = Qp[d] * scale;

    float m = -1e30f, lsum = 0.f;
    float o[64];
#pragma unroll
    for (int d = 0; d < 64; ++d) o[d] = 0.f;

    int numkt = 2 * (qb + 1);
    for (int kt = 0; kt < numkt; ++kt) {
        __syncthreads();
        const float* Kp = K + ((size_t)bh * Tt + kt * 64) * Dd;
        const float* Vp = V + ((size_t)bh * Tt + kt * 64) * Dd;
#pragma unroll
        for (int i = 0; i < 32; ++i) {
            int e = i * 128 + tid;
            ((float*)ks)[e] = Kp[e];
            ((float*)vs)[e] = Vp[e];
        }
        __syncthreads();
        int jend = qi - kt * 64 + 1;          // causal: key index <= qi
        if (jend > 64) jend = 64;
        for (int j = 0; j < jend; ++j) {
            float s = 0.f;
#pragma unroll
            for (int d = 0; d < 64; ++d) s += qreg[d] * ks[j][d];
            float mnew = fmaxf(m, s);
            float corr = __expf(m - mnew);
            float p = __expf(s - mnew);
            lsum = lsum * corr + p;
#pragma unroll
            for (int d = 0; d < 64; ++d) o[d] = o[d] * corr + p * vs[j][d];
            m = mnew;
        }
    }
    float inv = 1.f / lsum;
    float* Op = O + ((size_t)bb * Tt + qi) * Cc_ + hh * Dd;   // (B,T,H*D)
#pragma unroll
    for (int d = 0; d < 64; ++d) Op[d] = o[d] * inv;
}

// ---------------- launch ----------------
extern "C" void kernel_launch(void* const* d_in, const int* in_sizes, int n_in,
                              void* d_out, int out_size) {
    const int*   x     = (const int*)d_in[0];
    const float* tok   = (const float*)d_in[1];
    const float* pos   = (const float*)d_in[2];
    const float* Wq    = (const float*)d_in[3];
    const float* Wk    = (const float*)d_in[4];
    const float* Wv    = (const float*)d_in[5];
    const float* Wo    = (const float*)d_in[6];
    const float* bo    = (const float*)d_in[7];
    const float* ln1g  = (const float*)d_in[8];
    const float* ln1b  = (const float*)d_in[9];
    const float* ln2g  = (const float*)d_in[10];
    const float* ln2b  = (const float*)d_in[11];
    const float* W1    = (const float*)d_in[12];
    const float* b1    = (const float*)d_in[13];
    const float* W2    = (const float*)d_in[14];
    const float* b2    = (const float*)d_in[15];
    const float* lnfg  = (const float*)d_in[16];
    const float* lnfb  = (const float*)d_in[17];
    const float* Wh    = (const float*)d_in[18];
    const float* bh    = (const float*)d_in[19];
    float* out = (float*)d_out;

    float *h, *ln, *q, *k, *v, *att, *mid;
    cudaGetSymbolAddress((void**)&h,   d_h);
    cudaGetSymbolAddress((void**)&ln,  d_ln);
    cudaGetSymbolAddress((void**)&q,   d_q);
    cudaGetSymbolAddress((void**)&k,   d_k);
    cudaGetSymbolAddress((void**)&v,   d_v);
    cudaGetSymbolAddress((void**)&att, d_att);
    cudaGetSymbolAddress((void**)&mid, d_mid);

    embed_kernel<<<(Mm * Cc_ + 255) / 256, 256>>>(x, tok, pos, h);

    for (int l = 0; l < Ls; ++l) {
        ln_kernel<<<Mm, 256>>>(h, ln1g + l * Cc_, ln1b + l * Cc_, ln);
        qkv_kernel<<<dim3(Hh, Mm / 128), 256>>>(
            ln, Wq + (size_t)l * Hh * Cc_ * Dd, Wk + (size_t)l * Hh * Cc_ * Dd,
            Wv + (size_t)l * Hh * Cc_ * Dd, q, k, v);
        flash_kernel<<<dim3(Tt / 128, Bb * Hh), 128>>>(q, k, v, att);
        gemm128<false, true><<<dim3(Cc_ / 128, Mm / 128), 256>>>(
            att, Wo + (size_t)l * Cc_ * Cc_, bo + l * Cc_, h, h, Mm, Cc_, Cc_);
        ln_kernel<<<Mm, 256>>>(h, ln2g + l * Cc_, ln2b + l * Cc_, ln);
        gemm128<true, false><<<dim3(Ff / 128, Mm / 128), 256>>>(
            ln, W1 + (size_t)l * Cc_ * Ff, b1 + l * Ff, nullptr, mid, Mm, Ff, Cc_);
        gemm128<false, true><<<dim3(Cc_ / 128, Mm / 128), 256>>>(
            mid, W2 + (size_t)l * Ff * Cc_, b2 + l * Cc_, h, h, Mm, Cc_, Ff);
    }

    ln_kernel<<<Mm, 256>>>(h, lnfg, lnfb, ln);
    gemm128<false, false><<<dim3(Vv / 128, Mm / 128), 256>>>(
        ln, Wh, bh, nullptr, out, Mm, Vv, Cc_);
}

// round 10
// speedup vs baseline: 1.0048x; 1.0011x over previous
#include <cuda_runtime.h>
#include <cuda_bf16.h>
#include <math.h>

// Problem constants
#define Ls 6
#define Hh 12
#define Dd 64
#define Cc_ 768
#define Vv 32000
#define Bb 2
#define Tt 1024
#define Ff 3072           // 4*C
#define Mm (Bb*Tt)        // 2048

// ---------------- scratch (device globals: alloc-free) ----------------
__device__ float d_h  [Mm*Cc_];
__device__ float d_ln [Mm*Cc_];
__device__ float d_q  [Mm*Cc_];
__device__ float d_k  [Mm*Cc_];
__device__ float d_v  [Mm*Cc_];
__device__ float d_att[Mm*Cc_];
__device__ float d_mid[Mm*Ff];

// ---------------- helpers ----------------
__device__ __forceinline__ float blockReduceSum256(float v) {
    __shared__ float sh[33];
    int lane = threadIdx.x & 31, wid = threadIdx.x >> 5;
#pragma unroll
    for (int o = 16; o; o >>= 1) v += __shfl_xor_sync(0xffffffffu, v, o);
    if (lane == 0) sh[wid] = v;
    __syncthreads();
    if (wid == 0) {
        float t = (lane < 8) ? sh[lane] : 0.f;
#pragma unroll
        for (int o = 4; o; o >>= 1) t += __shfl_xor_sync(0xffffffffu, t, o);
        if (lane == 0) sh[32] = t;
    }
    __syncthreads();
    float r = sh[32];
    __syncthreads();   // allow safe reuse of sh on a second call
    return r;
}

// ---------------- embedding ----------------
__global__ void embed_kernel(const int* __restrict__ x,
                             const float* __restrict__ tok,
                             const float* __restrict__ pos,
                             float* __restrict__ h) {
    int i = blockIdx.x * blockDim.x + threadIdx.x;
    if (i >= Mm * Cc_) return;
    int m = i / Cc_, c = i - m * Cc_;
    int t = m % Tt;
    h[i] = tok[(size_t)x[m] * Cc_ + c] + pos[(size_t)t * Cc_ + c];
}

// ---------------- layernorm (1 row / block, 256 threads) ----------------
__global__ __launch_bounds__(256) void ln_kernel(const float* __restrict__ x,
                                                 const float* __restrict__ g,
                                                 const float* __restrict__ b,
                                                 float* __restrict__ out) {
    int row = blockIdx.x;
    const float* xr = x + (size_t)row * Cc_;
    int tid = threadIdx.x;
    float v0 = xr[tid], v1 = xr[tid + 256], v2 = xr[tid + 512];
    float s = blockReduceSum256(v0 + v1 + v2);
    float mean = s * (1.f / Cc_);
    float e0 = v0 - mean, e1 = v1 - mean, e2 = v2 - mean;
    float s2 = blockReduceSum256(e0 * e0 + e1 * e1 + e2 * e2);
    float rstd = rsqrtf(s2 * (1.f / Cc_) + 1e-5f);
    float* orow = out + (size_t)row * Cc_;
    orow[tid]       = e0 * rstd * g[tid]       + b[tid];
    orow[tid + 256] = e1 * rstd * g[tid + 256] + b[tid + 256];
    orow[tid + 512] = e2 * rstd * g[tid + 512] + b[tid + 512];
}

// ---------------- main SGEMM: C = A(MxK) @ B(KxN) + bias [+resid][relu] ----------------
// 128x128 tile, BK=8, 256 threads, 8x8 per thread
template <bool RELU, bool RESID>
__global__ __launch_bounds__(256) void gemm128(const float* __restrict__ A,
                                               const float* __restrict__ Bw,
                                               const float* __restrict__ bias,
                                               const float* __restrict__ Rz,
                                               float* __restrict__ Co,
                                               int M, int N, int K) {
    __shared__ float As[8][128];
    __shared__ float Bs[8][128];
    int tid = threadIdx.x;
    int m0 = blockIdx.y * 128;
    int n0 = blockIdx.x * 128;
    int arow = tid >> 1, acol = (tid & 1) << 2;
    int brow = tid >> 5, bcol = (tid & 31) << 2;
    int trow = (tid >> 4) << 3;
    int tcol = (tid & 15) << 3;
    float acc[8][8] = {};
    const float* Ap = A + (size_t)(m0 + arow) * K + acol;
    const float* Bp = Bw + (size_t)brow * N + n0 + bcol;

    for (int k0 = 0; k0 < K; k0 += 8) {
        float4 a = *(const float4*)(Ap + k0);
        As[acol + 0][arow] = a.x;
        As[acol + 1][arow] = a.y;
        As[acol + 2][arow] = a.z;
        As[acol + 3][arow] = a.w;
        float4 bv = *(const float4*)(Bp + (size_t)k0 * N);
        *(float4*)&Bs[brow][bcol] = bv;
        __syncthreads();
#pragma unroll
        for (int kk = 0; kk < 8; ++kk) {
            float4 ra0 = *(const float4*)&As[kk][trow];
            float4 ra1 = *(const float4*)&As[kk][trow + 4];
            float4 rb0 = *(const float4*)&Bs[kk][tcol];
            float4 rb1 = *(const float4*)&Bs[kk][tcol + 4];
            float ra[8] = {ra0.x, ra0.y, ra0.z, ra0.w, ra1.x, ra1.y, ra1.z, ra1.w};
            float rb[8] = {rb0.x, rb0.y, rb0.z, rb0.w, rb1.x, rb1.y, rb1.z, rb1.w};
#pragma unroll
            for (int i = 0; i < 8; ++i)
#pragma unroll
                for (int j = 0; j < 8; ++j) acc[i][j] += ra[i] * rb[j];
        }
        __syncthreads();
    }
#pragma unroll
    for (int i = 0; i < 8; ++i) {
        int row = m0 + trow + i;
#pragma unroll
        for (int j = 0; j < 8; ++j) {
            int col = n0 + tcol + j;
            float v = acc[i][j] + bias[col];
            if (RELU) v = fmaxf(v, 0.f);
            if (RESID) v += Rz[(size_t)row * N + col];
            Co[(size_t)row * N + col] = v;
        }
    }
}

// ---------------- fused QKV GEMM: per head, N=64 ----------------
// grid (H, M/128), 256 threads, 8x4 per thread per output
__global__ __launch_bounds__(256) void qkv_kernel(const float* __restrict__ A,
                                                  const float* __restrict__ Wq,
                                                  const float* __restrict__ Wk,
                                                  const float* __restrict__ Wv,
                                                  float* __restrict__ Qo,
                                                  float* __restrict__ Ko,
                                                  float* __restrict__ Vo) {
    __shared__ float As[8][128];
    __shared__ float Bq[8][64];
    __shared__ float Bk[8][64];
    __shared__ float Bv[8][64];
    int tid = threadIdx.x;
    int hh = blockIdx.x;
    int m0 = blockIdx.y * 128;
    int arow = tid >> 1, acol = (tid & 1) << 2;
    int brow = tid >> 5, bcol = (tid & 31) << 1;   // float2 across 64 cols
    int trow = (tid >> 4) << 3;
    int tcol = (tid & 15) << 2;
    float aq[8][4] = {}, ak[8][4] = {}, av[8][4] = {};
    const float* Ap  = A  + (size_t)(m0 + arow) * Cc_ + acol;
    const float* Wqp = Wq + ((size_t)hh * Cc_ + brow) * Dd + bcol;
    const float* Wkp = Wk + ((size_t)hh * Cc_ + brow) * Dd + bcol;
    const float* Wvp = Wv + ((size_t)hh * Cc_ + brow) * Dd + bcol;

    for (int k0 = 0; k0 < Cc_; k0 += 8) {
        float4 a = *(const float4*)(Ap + k0);
        As[acol + 0][arow] = a.x;
        As[acol + 1][arow] = a.y;
        As[acol + 2][arow] = a.z;
        As[acol + 3][arow] = a.w;
        size_t woff = (size_t)k0 * Dd;
        *(float2*)&Bq[brow][bcol] = *(const float2*)(Wqp + woff);
        *(float2*)&Bk[brow][bcol] = *(const float2*)(Wkp + woff);
        *(float2*)&Bv[brow][bcol] = *(const float2*)(Wvp + woff);
        __syncthreads();
#pragma unroll
        for (int kk = 0; kk < 8; ++kk) {
            float4 ra0 = *(const float4*)&As[kk][trow];
            float4 ra1 = *(const float4*)&As[kk][trow + 4];
            float ra[8] = {ra0.x, ra0.y, ra0.z, ra0.w, ra1.x, ra1.y, ra1.z, ra1.w};
            float4 rq = *(const float4*)&Bq[kk][tcol];
            float4 rk = *(const float4*)&Bk[kk][tcol];
            float4 rv = *(const float4*)&Bv[kk][tcol];
            float q4[4] = {rq.x, rq.y, rq.z, rq.w};
            float k4[4] = {rk.x, rk.y, rk.z, rk.w};
            float v4[4] = {rv.x, rv.y, rv.z, rv.w};
#pragma unroll
            for (int i = 0; i < 8; ++i)
#pragma unroll
                for (int j = 0; j < 4; ++j) {
                    aq[i][j] += ra[i] * q4[j];
                    ak[i][j] += ra[i] * k4[j];
                    av[i][j] += ra[i] * v4[j];
                }
        }
        __syncthreads();
    }
#pragma unroll
    for (int i = 0; i < 8; ++i) {
        int row = m0 + trow + i;
        int bb = row / Tt, t = row % Tt;
        size_t base = (((size_t)bb * Hh + hh) * Tt + t) * Dd + tcol;
        *(float4*)&Qo[base] = make_float4(aq[i][0], aq[i][1], aq[i][2], aq[i][3]);
        *(float4*)&Ko[base] = make_float4(ak[i][0], ak[i][1], ak[i][2], ak[i][3]);
        *(float4*)&Vo[base] = make_float4(av[i][0], av[i][1], av[i][2], av[i][3]);
    }
}

// ---------------- flash attention (fp32, online softmax) ----------------
// grid (T/128, B*H), 128 threads; each thread owns one query row
__global__ __launch_bounds__(128) void flash_kernel(const float* __restrict__ Q,
                                                    const float* __restrict__ K,
                                                    const float* __restrict__ V,
                                                    float* __restrict__ O) {
    __shared__ float ks[64][64];
    __shared__ float vs[64][64];
    int qb = blockIdx.x;
    int bh = blockIdx.y;
    int bb = bh / Hh, hh = bh % Hh;
    int tid = threadIdx.x;
    int qi = qb * 128 + tid;

    const float scale = rsqrtf((float)Cc_);
    float qreg[64];
    const float* Qp = Q + ((size_t)bh * Tt + qi) * Dd;
#pragma unroll
    for (int d = 0; d < 64; ++d) qreg[d] = Qp[d] * scale;

    float m = -1e30f, lsum = 0.f;
    float o[64];
#pragma unroll
    for (int d = 0; d < 64; ++d) o[d] = 0.f;

    int numkt = 2 * (qb + 1);
    for (int kt = 0; kt < numkt; ++kt) {
        __syncthreads();
        const float* Kp = K + ((size_t)bh * Tt + kt * 64) * Dd;
        const float* Vp = V + ((size_t)bh * Tt + kt * 64) * Dd;
#pragma unroll
        for (int i = 0; i < 32; ++i) {
            int e = i * 128 + tid;
            ((float*)ks)[e] = Kp[e];
            ((float*)vs)[e] = Vp[e];
        }
        __syncthreads();
        int jend = qi - kt * 64 + 1;          // causal: key index <= qi
        if (jend > 64) jend = 64;
        for (int j = 0; j < jend; ++j) {
            float s = 0.f;
#pragma unroll
            for (int d = 0; d < 64; ++d) s += qreg[d] * ks[j][d];
            float mnew = fmaxf(m, s);
            float corr = __expf(m - mnew);
            float p = __expf(s - mnew);
            lsum = lsum * corr + p;
#pragma unroll
            for (int d = 0; d < 64; ++d) o[d] = o[d] * corr + p * vs[j][d];
            m = mnew;
        }
    }
    float inv = 1.f / lsum;
    float* Op = O + ((size_t)bb * Tt + qi) * Cc_ + hh * Dd;   // (B,T,H*D)
#pragma unroll
    for (int d = 0; d < 64; ++d) Op[d] = o[d] * inv;
}

// ---------------- launch ----------------
extern "C" void kernel_launch(void* const* d_in, const int* in_sizes, int n_in,
                              void* d_out, int out_size) {
    const int*   x     = (const int*)d_in[0];
    const float* tok   = (const float*)d_in[1];
    const float* pos   = (const float*)d_in[2];
    const float* Wq    = (const float*)d_in[3];
    const float* Wk    = (const float*)d_in[4];
    const float* Wv    = (const float*)d_in[5];
    const float* Wo    = (const float*)d_in[6];
    const float* bo    = (const float*)d_in[7];
    const float* ln1g  = (const float*)d_in[8];
    const float* ln1b  = (const float*)d_in[9];
    const float* ln2g  = (const float*)d_in[10];
    const float* ln2b  = (const float*)d_in[11];
    const float* W1    = (const float*)d_in[12];
    const float* b1    = (const float*)d_in[13];
    const float* W2    = (const float*)d_in[14];
    const float* b2    = (const float*)d_in[15];
    const float* lnfg  = (const float*)d_in[16];
    const float* lnfb  = (const float*)d_in[17];
    const float* Wh    = (const float*)d_in[18];
    const float* bh    = (const float*)d_in[19];
    float* out = (float*)d_out;

    float *h, *ln, *q, *k, *v, *att, *mid;
    cudaGetSymbolAddress((void**)&h,   d_h);
    cudaGetSymbolAddress((void**)&ln,  d_ln);
    cudaGetSymbolAddress((void**)&q,   d_q);
    cudaGetSymbolAddress((void**)&k,   d_k);
    cudaGetSymbolAddress((void**)&v,   d_v);
    cudaGetSymbolAddress((void**)&att, d_att);
    cudaGetSymbolAddress((void**)&mid, d_mid);

    embed_kernel<<<(Mm * Cc_ + 255) / 256, 256>>>(x, tok, pos, h);

    for (int l = 0; l < Ls; ++l) {
        ln_kernel<<<Mm, 256>>>(h, ln1g + l * Cc_, ln1b + l * Cc_, ln);
        qkv_kernel<<<dim3(Hh, Mm / 128), 256>>>(
            ln, Wq + (size_t)l * Hh * Cc_ * Dd, Wk + (size_t)l * Hh * Cc_ * Dd,
            Wv + (size_t)l * Hh * Cc_ * Dd, q, k, v);
        flash_kernel<<<dim3(Tt / 128, Bb * Hh), 128>>>(q, k, v, att);
        gemm128<false, true><<<dim3(Cc_ / 128, Mm / 128), 256>>>(
            att, Wo + (size_t)l * Cc_ * Cc_, bo + l * Cc_, h, h, Mm, Cc_, Cc_);
        ln_kernel<<<Mm, 256>>>(h, ln2g + l * Cc_, ln2b + l * Cc_, ln);
        gemm128<true, false><<<dim3(Ff / 128, Mm / 128), 256>>>(
            ln, W1 + (size_t)l * Cc_ * Ff, b1 + l * Ff, nullptr, mid, Mm, Ff, Cc_);
        gemm128<false, true><<<dim3(Cc_ / 128, Mm / 128), 256>>>(
            mid, W2 + (size_t)l * Ff * Cc_, b2 + l * Cc_, h, h, Mm, Cc_, Ff);
    }

    ln_kernel<<<Mm, 256>>>(h, lnfg, lnfb, ln);
    gemm128<false, false><<<dim3(Vv / 128, Mm / 128), 256>>>(
        ln, Wh, bh, nullptr, out, Mm, Vv, Cc_);
}